// round 1
// baseline (speedup 1.0000x reference)
#include <cuda_runtime.h>
#include <math.h>

// Problem constants (from reference setup_inputs)
#define BATCH 128
#define NBOX  500
#define NCLS  80
#define NHEAD 6
#define NW    16           // 32-bit words per mask row (ceil(500/32))
#define IOU_THR 0.5f

// Output layout (float32, concatenated ravels of the tuple):
//   boxes_next (B,N,2) | scores (B,N) | labels (B,N) | nms_keep (B,N)
#define OFF_BOX   0
#define OFF_SCORE (BATCH*NBOX*2)
#define OFF_LAB   (OFF_SCORE + BATCH*NBOX)
#define OFF_KEEP  (OFF_LAB + BATCH*NBOX)

__global__ __launch_bounds__(512, 1)
void ddet_kernel(const float* __restrict__ boxes_t,
                 const float* __restrict__ pclass,
                 const float* __restrict__ pboxes,
                 const float* __restrict__ noise,
                 const float* __restrict__ fresh,
                 const float* __restrict__ ac,
                 const int*   __restrict__ tnow_p,
                 const int*   __restrict__ tnext_p,
                 float*       __restrict__ out)
{
    __shared__ float         s_score[NBOX];
    __shared__ float         s_c[NBOX];
    __shared__ float         s_w[NBOX];      // clamped width
    __shared__ float         s_x1[NBOX], s_x2[NBOX], s_ws[NBOX];   // sorted
    __shared__ unsigned char s_lab[NBOX], s_labs[NBOX];
    __shared__ unsigned short s_order[NBOX];
    __shared__ unsigned int  s_mask[NBOX * NW];   // 32 KB
    __shared__ unsigned int  s_sup[NW];

    const int b   = blockIdx.x;
    const int tid = threadIdx.x;

    const int tnow  = tnow_p[0];
    const int tnext = tnext_p[0];
    const float a  = ac[tnow];
    const float an = ac[tnext];
    const float sr    = sqrtf(1.0f / a);
    const float srm1  = sqrtf(1.0f / a - 1.0f);
    const float san   = sqrtf(an);
    const float sg    = sqrtf((1.0f - a / an) * (1.0f - an) / (1.0f - a)); // ETA=1
    const float ccv   = sqrtf(1.0f - an - sg * sg);

    const size_t head5_cls = (size_t)(NHEAD - 1) * BATCH * NBOX * NCLS;
    const float* pc5  = pclass + head5_cls + (size_t)b * NBOX * NCLS;
    const float* pc50 = pclass + head5_cls;                       // batch 0
    const float* pb5  = pboxes + (size_t)(NHEAD - 1) * BATCH * NBOX * 2
                               + (size_t)b * NBOX * 2;

    if (tid < NBOX) {
        const int n = tid;

        // ---- softmax scores / labels over 80 classes (keep first 79) ----
        const float4* row = (const float4*)(pc5 + (size_t)n * NCLS);
        float m80 = -INFINITY;
        #pragma unroll
        for (int c4 = 0; c4 < NCLS / 4; c4++) {
            float4 v = row[c4];
            m80 = fmaxf(m80, fmaxf(fmaxf(v.x, v.y), fmaxf(v.z, v.w)));
        }
        float sum = 0.0f;
        float best = -INFINITY;
        int   bi = 0;
        #pragma unroll
        for (int c4 = 0; c4 < NCLS / 4; c4++) {
            float4 v = row[c4];
            sum += expf(v.x - m80) + expf(v.y - m80)
                 + expf(v.z - m80) + expf(v.w - m80);
            const float vv[4] = {v.x, v.y, v.z, v.w};
            #pragma unroll
            for (int k = 0; k < 4; k++) {
                int c = c4 * 4 + k;
                if (c < NCLS - 1 && vv[k] > best) { best = vv[k]; bi = c; }
            }
        }
        const float score = expf(best - m80) / sum;
        s_score[n] = score;
        s_lab[n]   = (unsigned char)bi;
        out[OFF_SCORE + b * NBOX + n] = score;
        out[OFF_LAB   + b * NBOX + n] = (float)bi;

        // ---- keep mask from batch-0 sigmoid: max logit > 0 ----
        const float4* row0 = (const float4*)(pc50 + (size_t)n * NCLS);
        float mk = -INFINITY;
        #pragma unroll
        for (int c4 = 0; c4 < NCLS / 4; c4++) {
            float4 v = row0[c4];
            mk = fmaxf(mk, fmaxf(fmaxf(v.x, v.y), fmaxf(v.z, v.w)));
        }
        const bool keep0 = (mk > 0.0f);

        // ---- DDIM update (boxes_next) ----
        #pragma unroll
        for (int d = 0; d < 2; d++) {
            const int gi = (b * NBOX + n) * 2 + d;
            const float bs = pb5[n * 2 + d];
            const float bt = boxes_t[gi];
            const float pn = (sr * bt - bs) / srm1;
            const float upd = bs * san + ccv * pn + sg * noise[gi];
            out[OFF_BOX + gi] = keep0 ? upd : fresh[gi];
        }

        // ---- NMS geometry inputs ----
        const float cc_ = pb5[n * 2 + 0];
        const float ww_ = fmaxf(pb5[n * 2 + 1], 0.0001f);
        s_c[n] = cc_;
        s_w[n] = ww_;
    }
    __syncthreads();

    // ---- stable descending rank sort (matches jnp.argsort(-scores)) ----
    if (tid < NBOX) {
        const float si = s_score[tid];
        int r = 0;
        for (int j = 0; j < NBOX; j++) {
            const float sj = s_score[j];
            r += (sj > si) || (sj == si && j < tid);
        }
        s_order[r] = (unsigned short)tid;
    }
    __syncthreads();

    // ---- gather sorted boxes ----
    if (tid < NBOX) {
        const int o = s_order[tid];
        const float c = s_c[o];
        const float w = s_w[o];
        s_x1[tid]  = c - 0.5f * w;
        s_x2[tid]  = c + 0.5f * w;
        s_ws[tid]  = w;
        s_labs[tid] = s_lab[o];
    }
    __syncthreads();

    // ---- build suppression-candidate bitmask (j > i, iou > thr, same label) ----
    for (int task = tid; task < NBOX * NW; task += 512) {
        const int i  = task >> 4;        // row (0..499)
        const int w  = task & 15;        // word
        const int jb = w << 5;
        unsigned int bits = 0;
        if (jb + 31 > i) {
            const float x1i = s_x1[i], x2i = s_x2[i], wi = s_ws[i];
            const int   li  = s_labs[i];
            const int j0 = (jb > i + 1) ? jb : (i + 1);
            const int j1 = (jb + 32 < NBOX) ? (jb + 32) : NBOX;
            for (int j = j0; j < j1; j++) {
                float inter = fminf(x2i, s_x2[j]) - fmaxf(x1i, s_x1[j]);
                inter = fmaxf(inter, 0.0f);
                float un = fmaxf(wi + s_ws[j] - inter, 1e-9f);
                if (inter > IOU_THR * un && s_labs[j] == li)
                    bits |= 1u << (j - jb);
            }
        }
        s_mask[i * NW + w] = bits;
    }
    __syncthreads();

    // ---- greedy scan: warp 0, suppressed words register-resident ----
    if (tid < 32) {
        unsigned int myw = 0;
        const int lane = tid;
        for (int i = 0; i < NBOX; i++) {
            const unsigned int sw = __shfl_sync(0xffffffffu, myw, i >> 5);
            if (!((sw >> (i & 31)) & 1u) && lane < NW)
                myw |= s_mask[i * NW + lane];
        }
        if (lane < NW) s_sup[lane] = myw;
    }
    __syncthreads();

    // ---- scatter keep back to original order ----
    if (tid < NBOX) {
        const int o = s_order[tid];
        const bool kept = !((s_sup[tid >> 5] >> (tid & 31)) & 1u);
        out[OFF_KEEP + b * NBOX + o] = kept ? 1.0f : 0.0f;
    }
}

extern "C" void kernel_launch(void* const* d_in, const int* in_sizes, int n_in,
                              void* d_out, int out_size)
{
    const float* boxes_t = (const float*)d_in[0];
    const float* pclass  = (const float*)d_in[1];
    const float* pboxes  = (const float*)d_in[2];
    const float* noise   = (const float*)d_in[3];
    const float* fresh   = (const float*)d_in[4];
    const float* ac      = (const float*)d_in[5];
    const int*   tnow    = (const int*)d_in[6];
    const int*   tnext   = (const int*)d_in[7];
    float* out = (float*)d_out;

    ddet_kernel<<<BATCH, 512>>>(boxes_t, pclass, pboxes, noise, fresh,
                                ac, tnow, tnext, out);
}

// round 2
// speedup vs baseline: 3.7138x; 3.7138x over previous
#include <cuda_runtime.h>
#include <math.h>

// Problem constants
#define BATCH 128
#define NBOX  500
#define NCLS  80
#define NHEAD 6
#define NW    16            // 32-bit words per mask row (ceil(500/32))
#define MSTR  17            // padded mask row stride (words) -> conflict-free

// Output layout (float32): boxes_next (B,N,2) | scores (B,N) | labels (B,N) | keep (B,N)
#define OFF_SCORE (BATCH*NBOX*2)
#define OFF_LAB   (OFF_SCORE + BATCH*NBOX)
#define OFF_KEEP  (OFF_LAB + BATCH*NBOX)

__global__ __launch_bounds__(512, 1)
void ddet_kernel(const float* __restrict__ boxes_t,
                 const float* __restrict__ pclass,
                 const float* __restrict__ pboxes,
                 const float* __restrict__ noise,
                 const float* __restrict__ fresh,
                 const float* __restrict__ ac,
                 const int*   __restrict__ tnow_p,
                 const int*   __restrict__ tnext_p,
                 float*       __restrict__ out)
{
    __shared__ unsigned int   s_mask[512 * MSTR];          // 34.8 KB (also used as u_box staging)
    __shared__ float4         s_box4[NBOX];                // sorted {x1,x2,w,label}
    __shared__ __align__(16) float s_score[NBOX];
    __shared__ unsigned short s_order[NBOX];
    __shared__ unsigned char  s_lab[NBOX];
    __shared__ unsigned char  s_keep[NBOX];
    __shared__ unsigned int   s_sup[NW];

    const int b   = blockIdx.x;
    const int tid = threadIdx.x;

    const int   tnow  = tnow_p[0];
    const int   tnext = tnext_p[0];
    const float a     = ac[tnow];
    const float an    = ac[tnext];
    const float sr    = sqrtf(1.0f / a);
    const float srm1  = sqrtf(1.0f / a - 1.0f);
    const float san   = sqrtf(an);
    const float sg    = sqrtf((1.0f - a / an) * (1.0f - an) / (1.0f - a));  // ETA=1
    const float ccv   = sqrtf(1.0f - an - sg * sg);

    const float* pc5  = pclass + ((size_t)(NHEAD - 1) * BATCH + b) * NBOX * NCLS;
    const float* pc50 = pclass + (size_t)(NHEAD - 1) * BATCH * NBOX * NCLS;   // batch 0
    const float* pb5  = pboxes + ((size_t)(NHEAD - 1) * BATCH + b) * NBOX * 2;

    // ================= Phase 1: softmax scores/labels + keep mask =================
    // 4 threads per row; each lane holds 20 logits (5 float4) register-resident.
    {
        const int g = tid >> 2;       // row group 0..127
        const int q = tid & 3;        // quarter of the row
        for (int pass = 0; pass < 4; pass++) {
            const int row  = g + 128 * pass;
            const int rowc = (row < NBOX) ? row : (NBOX - 1);

            const float4* rp = (const float4*)(pc5  + (size_t)rowc * NCLS) + q * 5;
            const float4* kp = (const float4*)(pc50 + (size_t)rowc * NCLS) + q * 5;
            float4 v0 = rp[0], v1 = rp[1], v2 = rp[2], v3 = rp[3], v4 = rp[4];
            float4 k0 = kp[0], k1 = kp[1], k2 = kp[2], k3 = kp[3], k4 = kp[4];

            // lane-local max over 20
            float m = fmaxf(fmaxf(fmaxf(v0.x, v0.y), fmaxf(v0.z, v0.w)),
                     fmaxf(fmaxf(fmaxf(v1.x, v1.y), fmaxf(v1.z, v1.w)),
                     fmaxf(fmaxf(fmaxf(v2.x, v2.y), fmaxf(v2.z, v2.w)),
                     fmaxf(fmaxf(fmaxf(v3.x, v3.y), fmaxf(v3.z, v3.w)),
                           fmaxf(fmaxf(v4.x, v4.y), fmaxf(v4.z, v4.w))))));
            // lane-local exp-sum
            float s =  __expf(v0.x - m) + __expf(v0.y - m) + __expf(v0.z - m) + __expf(v0.w - m)
                     + __expf(v1.x - m) + __expf(v1.y - m) + __expf(v1.z - m) + __expf(v1.w - m)
                     + __expf(v2.x - m) + __expf(v2.y - m) + __expf(v2.z - m) + __expf(v2.w - m)
                     + __expf(v3.x - m) + __expf(v3.y - m) + __expf(v3.z - m) + __expf(v3.w - m)
                     + __expf(v4.x - m) + __expf(v4.y - m) + __expf(v4.z - m) + __expf(v4.w - m);
            // lane-local argmax over classes != 79 (first-index tie rule via strict >)
            float best = -INFINITY; int bi = 0;
            {
                const float vv[20] = { v0.x,v0.y,v0.z,v0.w, v1.x,v1.y,v1.z,v1.w,
                                       v2.x,v2.y,v2.z,v2.w, v3.x,v3.y,v3.z,v3.w,
                                       v4.x,v4.y,v4.z,v4.w };
                #pragma unroll
                for (int kk = 0; kk < 20; kk++) {
                    const int c = q * 20 + kk;
                    if (c < NCLS - 1 && vv[kk] > best) { best = vv[kk]; bi = c; }
                }
            }
            // lane-local keep max
            float km = fmaxf(fmaxf(fmaxf(k0.x, k0.y), fmaxf(k0.z, k0.w)),
                      fmaxf(fmaxf(fmaxf(k1.x, k1.y), fmaxf(k1.z, k1.w)),
                      fmaxf(fmaxf(fmaxf(k2.x, k2.y), fmaxf(k2.z, k2.w)),
                      fmaxf(fmaxf(fmaxf(k3.x, k3.y), fmaxf(k3.z, k3.w)),
                            fmaxf(fmaxf(k4.x, k4.y), fmaxf(k4.z, k4.w))))));

            // merge the 4 lanes of the row (butterfly)
            #pragma unroll
            for (int off = 1; off <= 2; off <<= 1) {
                const float m2  = __shfl_xor_sync(0xffffffffu, m,    off);
                const float s2  = __shfl_xor_sync(0xffffffffu, s,    off);
                const float b2  = __shfl_xor_sync(0xffffffffu, best, off);
                const int   bi2 = __shfl_xor_sync(0xffffffffu, bi,   off);
                const float km2 = __shfl_xor_sync(0xffffffffu, km,   off);
                const float nm = fmaxf(m, m2);
                s = s * __expf(m - nm) + s2 * __expf(m2 - nm);
                m = nm;
                if (b2 > best || (b2 == best && bi2 < bi)) { best = b2; bi = bi2; }
                km = fmaxf(km, km2);
            }
            if (q == 0 && row < NBOX) {
                s_score[row] = __fdividef(__expf(best - m), s);
                s_lab[row]   = (unsigned char)bi;
                s_keep[row]  = (km > 0.0f) ? 1 : 0;   // sigmoid(x)>0.5 <=> x>0
            }
        }
    }
    __syncthreads();

    // ======== Phase 2: DDIM update + score/label outputs + NMS box staging ========
    float4* u_box = (float4*)s_mask;   // {c, w_clamped, label, 0} in original order
    if (tid < NBOX) {
        const int n = tid;
        const float2 cw = ((const float2*)pb5)[n];

        const float score = s_score[n];
        const int   lab   = s_lab[n];
        out[OFF_SCORE + b * NBOX + n] = score;
        out[OFF_LAB   + b * NBOX + n] = (float)lab;

        const bool keep0 = s_keep[n];
        const float2 bt = ((const float2*)boxes_t)[b * NBOX + n];
        const float2 nz = ((const float2*)noise)[b * NBOX + n];
        const float2 fr = ((const float2*)fresh)[b * NBOX + n];
        float2 o;
        {
            const float pnx = (sr * bt.x - cw.x) / srm1;
            const float pny = (sr * bt.y - cw.y) / srm1;
            o.x = keep0 ? (cw.x * san + ccv * pnx + sg * nz.x) : fr.x;
            o.y = keep0 ? (cw.y * san + ccv * pny + sg * nz.y) : fr.y;
        }
        ((float2*)out)[b * NBOX + n] = o;

        u_box[n] = make_float4(cw.x, fmaxf(cw.y, 0.0001f), (float)lab, 0.0f);
    }
    __syncthreads();

    // ============ Phase 3: stable descending rank sort (matches argsort) ==========
    if (tid < NBOX) {
        const float si = s_score[tid];
        const float4* sc4 = (const float4*)s_score;
        int r = 0;
        #pragma unroll 5
        for (int j4 = 0; j4 < NBOX / 4; j4++) {
            const float4 v = sc4[j4];
            const int j = 4 * j4;
            r += (v.x > si) || (v.x == si && (j + 0) < tid);
            r += (v.y > si) || (v.y == si && (j + 1) < tid);
            r += (v.z > si) || (v.z == si && (j + 2) < tid);
            r += (v.w > si) || (v.w == si && (j + 3) < tid);
        }
        s_order[r] = (unsigned short)tid;
    }
    __syncthreads();

    // ===================== Phase 4: gather sorted box geometry ====================
    if (tid < NBOX) {
        const int o = s_order[tid];
        const float4 u = u_box[o];
        s_box4[tid] = make_float4(u.x - 0.5f * u.y, u.x + 0.5f * u.y, u.y, u.z);
    }
    __syncthreads();

    // ====== Phase 5: suppression-candidate bitmask, upper triangle only ===========
    // One thread per sorted row i; all lanes iterate the same j -> broadcast LDS.128.
    // iou > 0.5  <=>  3*inter > wi + wj   (clamps provably redundant)
    if (tid < NBOX) {
        const int i = tid;
        const float4 bi4 = s_box4[i];
        const float x1i = bi4.x, x2i = bi4.y, wi = bi4.z, li = bi4.w;
        const int kb0 = i >> 5;                 // warp-uniform (warps are 32-aligned)
        for (int kb = kb0; kb < NW; kb++) {
            unsigned int bits = 0;
            const int j0 = kb * 32;
            const int j1 = (j0 + 32 < NBOX) ? j0 + 32 : NBOX;
            #pragma unroll 4
            for (int j = j0; j < j1; j++) {
                const float4 bj = s_box4[j];                      // broadcast
                const float inter = fminf(x2i, bj.y) - fmaxf(x1i, bj.x);
                const bool cond = (3.0f * inter > wi + bj.z) && (li == bj.w);
                bits |= ((unsigned int)cond) << (j - j0);
            }
            if (kb == kb0) {                                      // keep only j > i
                const int sh = (i & 31) + 1;
                bits = (sh == 32) ? 0u : (bits & (0xFFFFFFFFu << sh));
            }
            s_mask[i * MSTR + kb] = bits;
        }
    } else {                                    // rows 500..511: zero (read by greedy)
        #pragma unroll
        for (int kb = 0; kb < NW; kb++) s_mask[tid * MSTR + kb] = 0;
    }
    __syncthreads();

    // ================= Phase 6: blocked greedy scan (warp 0 only) =================
    if (tid < 32) {
        const int lane = tid;
        unsigned int sup = 0;                   // lane l (<16): suppressed bits, block l
        for (int k = 0; k < NW; k++) {
            const unsigned int diag = s_mask[(32 * k + lane) * MSTR + k];
            unsigned int cur = __shfl_sync(0xffffffffu, sup, k);
            #pragma unroll
            for (int i = 0; i < 32; i++) {
                const unsigned int di = __shfl_sync(0xffffffffu, diag, i);
                const unsigned int msk =
                    (unsigned int)(((int)(cur << (31 - i))) >> 31);  // all-ones if bit i set
                cur |= di & ~msk;
            }
            if (lane == k) sup = cur;
            if (lane > k && lane < NW) {
                const unsigned int keepb = ~cur;
                for (int i = 0; i < 32; i++) {
                    if ((keepb >> i) & 1u)
                        sup |= s_mask[(32 * k + i) * MSTR + lane];
                }
            }
        }
        if (lane < NW) s_sup[lane] = sup;
    }
    __syncthreads();

    // ================= Phase 7: scatter keep back to original order ===============
    if (tid < NBOX) {
        const int o = s_order[tid];
        const bool kept = !((s_sup[tid >> 5] >> (tid & 31)) & 1u);
        out[OFF_KEEP + b * NBOX + o] = kept ? 1.0f : 0.0f;
    }
}

extern "C" void kernel_launch(void* const* d_in, const int* in_sizes, int n_in,
                              void* d_out, int out_size)
{
    const float* boxes_t = (const float*)d_in[0];
    const float* pclass  = (const float*)d_in[1];
    const float* pboxes  = (const float*)d_in[2];
    const float* noise   = (const float*)d_in[3];
    const float* fresh   = (const float*)d_in[4];
    const float* ac      = (const float*)d_in[5];
    const int*   tnow    = (const int*)d_in[6];
    const int*   tnext   = (const int*)d_in[7];
    float* out = (float*)d_out;

    ddet_kernel<<<BATCH, 512>>>(boxes_t, pclass, pboxes, noise, fresh,
                                ac, tnow, tnext, out);
}